// round 3
// baseline (speedup 1.0000x reference)
#include <cuda_runtime.h>

// Problem constants
#define BQ 4
#define NP 8192
#define SQ 2048
#define CF 16
#define KN 32
constexpr int   P   = BQ * SQ * KN;      // 262144 points total
constexpr float R2  = 0.25f;             // radius^2
constexpr double EPSD = 1e-5;

// ---------------- scratch (device globals; no allocation allowed) ----------
__device__ int    g_idx[P];                      // ball-query indices
__device__ int    g_valid[BQ * SQ];              // num>0 per query
__device__ float  g_y1[(size_t)P * 32];          // conv1 pre-BN
__device__ float  g_y2[(size_t)P * 32];          // conv2 pre-BN
__device__ float  g_y3[(size_t)P * 64];          // conv3 pre-BN
// [0:32)sum1 [32:64)sq1 [64:96)sum2 [96:128)sq2 [128:192)sum3 [192:256)sq3
__device__ double g_stats[256];
// [0:32)a1 [32:64)c1 [64:96)a2 [96:128)c2 [128:192)a3 [192:256)c3
__device__ float  g_ab[256];

// ---------------- kernels --------------------------------------------------

__global__ void zero_stats_kernel() {
    int i = threadIdx.x;
    if (i < 256) g_stats[i] = 0.0;
}

// Warp-per-query ball query with exact first-K ordering via ballot + prefix popc.
__global__ __launch_bounds__(256) void ballquery_kernel(
    const float* __restrict__ pc, const float* __restrict__ newpc)
{
    int warp = (blockIdx.x * blockDim.x + threadIdx.x) >> 5;
    int lane = threadIdx.x & 31;
    int b = warp >> 11;          // / SQ
    int s = warp & 2047;
    const float* pcb = pc + b * 3 * NP;
    const float* np  = newpc + b * 3 * SQ + s;
    float qx = np[0], qy = np[SQ], qz = np[2 * SQ];

    int count = 0, firstidx = 0;
    int* out = g_idx + warp * KN;

    for (int j0 = 0; j0 < NP; j0 += 32) {
        int j = j0 + lane;
        float dx = pcb[j]          - qx;
        float dy = pcb[NP + j]     - qy;
        float dz = pcb[2 * NP + j] - qz;
        bool in = (dx * dx + dy * dy + dz * dz) < R2;
        unsigned m = __ballot_sync(0xffffffffu, in);
        if (m) {
            if (count == 0) firstidx = j0 + __ffs((int)m) - 1;
            if (in) {
                int slot = count + __popc(m & ((1u << lane) - 1u));
                if (slot < KN) out[slot] = j;
            }
            count += __popc(m);
            if (count >= KN) break;   // num only needed as >0; already known
        }
    }
    // Fill empty slots with first-found index (0 if none) — reference semantics.
    if (lane >= count) out[lane] = firstidx;
    if (lane == 0) g_valid[warp] = (count > 0) ? 1 : 0;
}

// Gather (pc diff + feat) and conv1 (19 -> 32). Writes y1 channel-last.
__global__ __launch_bounds__(256) void conv1_kernel(
    const float* __restrict__ pc, const float* __restrict__ feat,
    const float* __restrict__ newpc,
    const float* __restrict__ w1, const float* __restrict__ b1)
{
    __shared__ float sw[608];   // 32 x 19
    __shared__ float sb[32];
    int tid = threadIdx.x;
    for (int i = tid; i < 608; i += 256) sw[i] = w1[i];
    if (tid < 32) sb[tid] = b1[tid];
    __syncthreads();

    int p = blockIdx.x * 256 + tid;
    int q = p >> 5;
    int b = q >> 11;
    int s = q & 2047;
    int j = g_idx[p];

    const float* pcb = pc + b * 3 * NP;
    const float* np  = newpc + b * 3 * SQ + s;
    float x[19];
    x[0] = pcb[j]          - np[0];
    x[1] = pcb[NP + j]     - np[SQ];
    x[2] = pcb[2 * NP + j] - np[2 * SQ];
    const float* fb = feat + b * CF * NP + j;
    #pragma unroll
    for (int i = 0; i < 16; i++) x[3 + i] = __ldg(fb + i * NP);

    float4* dst = (float4*)(g_y1 + (size_t)p * 32);
    #pragma unroll
    for (int c4 = 0; c4 < 8; c4++) {
        float4 v;
        float* vp = &v.x;
        #pragma unroll
        for (int u = 0; u < 4; u++) {
            int c = c4 * 4 + u;
            float acc = sb[c];
            #pragma unroll
            for (int i = 0; i < 19; i++) acc = fmaf(sw[c * 19 + i], x[i], acc);
            vp[u] = acc;
        }
        dst[c4] = v;
    }
}

// Per-channel sum / sumsq reduction over [P, CH] channel-last tensor.
template <int CH, int LAYER>
__global__ __launch_bounds__(256) void stats_kernel()
{
    __shared__ double ss[CH], sq[CH];
    int tid = threadIdx.x;
    if (tid < CH) { ss[tid] = 0.0; sq[tid] = 0.0; }
    __syncthreads();

    const float* ybase = (LAYER == 0) ? g_y1 : ((LAYER == 1) ? g_y2 : g_y3);
    const float4* y4 = (const float4*)ybase;
    const int total4 = P * CH / 4;
    const int stride = gridDim.x * blockDim.x;   // 131072; 4*stride % CH == 0
    int i0 = blockIdx.x * 256 + tid;

    float a0 = 0, a1 = 0, a2 = 0, a3 = 0, q0 = 0, q1 = 0, q2 = 0, q3 = 0;
    for (int i = i0; i < total4; i += stride) {
        float4 v = y4[i];
        a0 += v.x; q0 += v.x * v.x;
        a1 += v.y; q1 += v.y * v.y;
        a2 += v.z; q2 += v.z * v.z;
        a3 += v.w; q3 += v.w * v.w;
    }
    int c0 = (4 * i0) & (CH - 1);   // channel of component .x, constant per thread
    atomicAdd(&ss[c0],     (double)a0); atomicAdd(&sq[c0],     (double)q0);
    atomicAdd(&ss[c0 + 1], (double)a1); atomicAdd(&sq[c0 + 1], (double)q1);
    atomicAdd(&ss[c0 + 2], (double)a2); atomicAdd(&sq[c0 + 2], (double)q2);
    atomicAdd(&ss[c0 + 3], (double)a3); atomicAdd(&sq[c0 + 3], (double)q3);
    __syncthreads();

    const int base = (LAYER == 0) ? 0 : ((LAYER == 1) ? 64 : 128);
    if (tid < CH) {
        atomicAdd(&g_stats[base + tid],      ss[tid]);
        atomicAdd(&g_stats[base + CH + tid], sq[tid]);
    }
}

// Turn (sum, sumsq, gamma, beta) into per-channel affine (a, c).
__global__ void finalize_kernel(const float* __restrict__ gam,
                                const float* __restrict__ bet, int layer)
{
    int i = threadIdx.x;
    int CH = (layer == 2) ? 64 : 32;
    if (i < CH) {
        int base = (layer == 0) ? 0 : ((layer == 1) ? 64 : 128);
        double m = g_stats[base + i] * (1.0 / (double)P);
        double v = g_stats[base + CH + i] * (1.0 / (double)P) - m * m;
        double a = (double)gam[i] / sqrt(v + EPSD);
        g_ab[base + i]      = (float)a;
        g_ab[base + CH + i] = (float)((double)bet[i] - m * a);
    }
}

// conv2: z = relu(a1*y1+c1); y2 = w2 @ z + b2
__global__ __launch_bounds__(256) void conv2_kernel(
    const float* __restrict__ w2, const float* __restrict__ b2)
{
    __shared__ float sw[1024], sb[32], sa[32], sc[32];
    int tid = threadIdx.x;
    for (int i = tid; i < 1024; i += 256) sw[i] = w2[i];
    if (tid < 32) { sb[tid] = b2[tid]; sa[tid] = g_ab[tid]; sc[tid] = g_ab[32 + tid]; }
    __syncthreads();

    int p = blockIdx.x * 256 + tid;
    const float4* src = (const float4*)(g_y1 + (size_t)p * 32);
    float z[32];
    #pragma unroll
    for (int i = 0; i < 8; i++) {
        float4 v = src[i];
        z[4*i]   = fmaxf(fmaf(sa[4*i],   v.x, sc[4*i]),   0.f);
        z[4*i+1] = fmaxf(fmaf(sa[4*i+1], v.y, sc[4*i+1]), 0.f);
        z[4*i+2] = fmaxf(fmaf(sa[4*i+2], v.z, sc[4*i+2]), 0.f);
        z[4*i+3] = fmaxf(fmaf(sa[4*i+3], v.w, sc[4*i+3]), 0.f);
    }
    float4* dst = (float4*)(g_y2 + (size_t)p * 32);
    #pragma unroll
    for (int c4 = 0; c4 < 8; c4++) {
        float4 o;
        float* op = &o.x;
        #pragma unroll
        for (int u = 0; u < 4; u++) {
            int c = c4 * 4 + u;
            float acc = sb[c];
            #pragma unroll
            for (int i = 0; i < 32; i++) acc = fmaf(sw[c * 32 + i], z[i], acc);
            op[u] = acc;
        }
        dst[c4] = o;
    }
}

// conv3: z = relu(a2*y2+c2); y3 = w3 @ z + b3 (32 -> 64), half-channel split.
__global__ __launch_bounds__(256) void conv3_kernel(
    const float* __restrict__ w3, const float* __restrict__ b3)
{
    __shared__ float sw[2048], sb[64], sa[32], sc[32];
    int tid = threadIdx.x;
    for (int i = tid; i < 2048; i += 256) sw[i] = w3[i];
    if (tid < 64) sb[tid] = b3[tid];
    if (tid < 32) { sa[tid] = g_ab[64 + tid]; sc[tid] = g_ab[96 + tid]; }
    __syncthreads();

    int g = blockIdx.x * 256 + tid;
    int p = g >> 1, h = g & 1;
    const float4* src = (const float4*)(g_y2 + (size_t)p * 32);
    float z[32];
    #pragma unroll
    for (int i = 0; i < 8; i++) {
        float4 v = src[i];
        z[4*i]   = fmaxf(fmaf(sa[4*i],   v.x, sc[4*i]),   0.f);
        z[4*i+1] = fmaxf(fmaf(sa[4*i+1], v.y, sc[4*i+1]), 0.f);
        z[4*i+2] = fmaxf(fmaf(sa[4*i+2], v.z, sc[4*i+2]), 0.f);
        z[4*i+3] = fmaxf(fmaf(sa[4*i+3], v.w, sc[4*i+3]), 0.f);
    }
    int cb = h * 32;
    float4* dst = (float4*)(g_y3 + (size_t)p * 64 + cb);
    #pragma unroll
    for (int c4 = 0; c4 < 8; c4++) {
        float4 o;
        float* op = &o.x;
        #pragma unroll
        for (int u = 0; u < 4; u++) {
            int c = cb + c4 * 4 + u;
            float acc = sb[c];
            #pragma unroll
            for (int i = 0; i < 32; i++) acc = fmaf(sw[c * 32 + i], z[i], acc);
            op[u] = acc;
        }
        dst[c4] = o;
    }
}

// Final: out = relu(a3*y3+c3) * (num>0), transposed to [B,64,S,K] via smem tile.
__global__ __launch_bounds__(256) void out_kernel(float* __restrict__ out)
{
    __shared__ float tile[64 * 65];
    __shared__ float sa[64], sc[64];
    int tid = threadIdx.x;
    if (tid < 64) { sa[tid] = g_ab[128 + tid]; sc[tid] = g_ab[192 + tid]; }
    __syncthreads();

    int pt0 = blockIdx.x * 64;          // 64 points per tile (never crosses batch)
    int b  = pt0 >> 16;                  // 65536 points per batch
    int w0 = pt0 & 65535;
    const float* src = g_y3 + (size_t)pt0 * 64;

    #pragma unroll
    for (int it = 0; it < 16; it++) {
        int flat = it * 256 + tid;       // coalesced read
        int p = flat >> 6, c = flat & 63;
        float v = src[flat];
        float val = fmaxf(fmaf(sa[c], v, sc[c]), 0.f);
        val *= (float)g_valid[(pt0 + p) >> 5];
        tile[p * 65 + c] = val;
    }
    __syncthreads();

    float* ob = out + (size_t)b * 64 * 65536 + w0;
    #pragma unroll
    for (int it = 0; it < 16; it++) {
        int flat = it * 256 + tid;
        int c = flat >> 6, p = flat & 63;
        ob[(size_t)c * 65536 + p] = tile[p * 65 + c];  // coalesced write
    }
}

// ---------------- launch ---------------------------------------------------

extern "C" void kernel_launch(void* const* d_in, const int* in_sizes, int n_in,
                              void* d_out, int out_size)
{
    const float* pc   = (const float*)d_in[0];
    const float* feat = (const float*)d_in[1];
    const float* npc  = (const float*)d_in[2];
    const float* w1   = (const float*)d_in[3];
    const float* b1   = (const float*)d_in[4];
    const float* g1   = (const float*)d_in[5];
    const float* be1  = (const float*)d_in[6];
    const float* w2   = (const float*)d_in[7];
    const float* b2   = (const float*)d_in[8];
    const float* g2   = (const float*)d_in[9];
    const float* be2  = (const float*)d_in[10];
    const float* w3   = (const float*)d_in[11];
    const float* b3   = (const float*)d_in[12];
    const float* g3   = (const float*)d_in[13];
    const float* be3  = (const float*)d_in[14];
    float* out = (float*)d_out;

    zero_stats_kernel<<<1, 256>>>();
    ballquery_kernel<<<(BQ * SQ) / 8, 256>>>(pc, npc);          // 1024 blocks
    conv1_kernel<<<P / 256, 256>>>(pc, feat, npc, w1, b1);      // 1024 blocks
    stats_kernel<32, 0><<<512, 256>>>();
    finalize_kernel<<<1, 64>>>(g1, be1, 0);
    conv2_kernel<<<P / 256, 256>>>(w2, b2);
    stats_kernel<32, 1><<<512, 256>>>();
    finalize_kernel<<<1, 64>>>(g2, be2, 1);
    conv3_kernel<<<(2 * P) / 256, 256>>>(w3, b3);               // 2048 blocks
    stats_kernel<64, 2><<<512, 256>>>();
    finalize_kernel<<<1, 64>>>(g3, be3, 2);
    out_kernel<<<P / 64, 256>>>(out);                            // 4096 blocks
}

// round 4
// speedup vs baseline: 1.7146x; 1.7146x over previous
#include <cuda_runtime.h>

#define BQ 4
#define NP 8192
#define SQ 2048
#define CF 16
#define KN 32
constexpr int    P    = BQ * SQ * KN;        // 262144 points
constexpr float  R2   = 0.25f;
constexpr double EPSD = 1e-5;
constexpr double INVP = 1.0 / (double)P;

// ---------------- scratch ----------------
__device__ int    g_valid[BQ * SQ];
__device__ float  g_featT[(size_t)BQ * NP * CF];   // [b][j][c] point-major
__device__ float  g_y1[(size_t)P * 32];
__device__ float  g_y2[(size_t)P * 32];
__device__ float  g_y3[(size_t)P * 64];
// [0:32)sum1 [32:64)sq1 [64:96)sum2 [96:128)sq2 [128:192)sum3 [192:256)sq3
__device__ double g_stats[256];

// ---------------- f32x2 helpers ----------------
__device__ __forceinline__ unsigned long long pack2(float a, float b) {
    unsigned long long r;
    asm("mov.b64 %0, {%1, %2};" : "=l"(r) : "f"(a), "f"(b));
    return r;
}
__device__ __forceinline__ unsigned long long dup2(float a) {
    unsigned long long r;
    asm("mov.b64 %0, {%1, %1};" : "=l"(r) : "f"(a));
    return r;
}
__device__ __forceinline__ void fma2(unsigned long long& d,
                                     unsigned long long a, unsigned long long b) {
    asm("fma.rn.f32x2 %0, %1, %2, %0;" : "+l"(d) : "l"(a), "l"(b));
}
__device__ __forceinline__ float2 unpack2(unsigned long long v) {
    float lo, hi;
    asm("mov.b64 {%0, %1}, %2;" : "=f"(lo), "=f"(hi) : "l"(v));
    return make_float2(lo, hi);
}

// Warp transpose-fold: on entry s[c]/t[c] hold per-lane values for channel c.
// On exit, osum/osq = warp totals for channel `lane`. Destroys s, t.
__device__ __forceinline__ void warp_fold(float* s, float* t, int lane,
                                          float& osum, float& osq) {
    #pragma unroll
    for (int st = 0; st < 5; st++) {
        int wbit = 1 << st;
        bool hi = (lane & wbit) != 0;
        #pragma unroll
        for (int k = 0; k < (16 >> st); k++) {
            float slo = s[2 * k], shi = s[2 * k + 1];
            float ssend = hi ? slo : shi;
            float skeep = hi ? shi : slo;
            s[k] = skeep + __shfl_xor_sync(0xffffffffu, ssend, wbit);
            float tlo = t[2 * k], thi = t[2 * k + 1];
            float tsend = hi ? tlo : thi;
            float tkeep = hi ? thi : tlo;
            t[k] = tkeep + __shfl_xor_sync(0xffffffffu, tsend, wbit);
        }
    }
    osum = s[0]; osq = t[0];
}

// ---------------- prep: zero stats + transpose feat to point-major ----------
__global__ __launch_bounds__(256) void prep_kernel(const float* __restrict__ feat) {
    __shared__ float tile[16][65];
    int tid = threadIdx.x;
    if (blockIdx.x == 0) g_stats[tid] = 0.0;     // 256 threads, 256 entries
    int b  = blockIdx.x >> 7;
    int j0 = (blockIdx.x & 127) * 64;
    const float* f = feat + (size_t)b * CF * NP;
    #pragma unroll
    for (int i = tid; i < 1024; i += 256) {
        int c = i >> 6, jj = i & 63;
        tile[c][jj] = f[(size_t)c * NP + j0 + jj];
    }
    __syncthreads();
    float* o = g_featT + ((size_t)b * NP + j0) * CF;
    #pragma unroll
    for (int i = tid; i < 1024; i += 256) {
        int jj = i >> 4, c = i & 15;
        o[i] = tile[c][jj];
    }
}

// ---------------- k1: ball query + gather + conv1 + stats1 -----------------
// 256 blocks x 256 threads; 32 queries/block (4 per warp), pc batch in smem.
__global__ __launch_bounds__(256) void k1_kernel(
    const float* __restrict__ pc, const float* __restrict__ newpc,
    const float* __restrict__ w1, const float* __restrict__ b1)
{
    extern __shared__ float spc[];                 // 3*NP floats (96 KB)
    __shared__ unsigned long long swp[19 * 16];    // w1 channel-pairs
    __shared__ unsigned long long sbp[16];
    __shared__ float bss[32], bsq[32];
    __shared__ int   sIdx[8][KN];

    int tid = threadIdx.x, lane = tid & 31, w = tid >> 5;
    int qb = blockIdx.x * 32;                      // global query base
    int b  = qb >> 11;

    const float4* src = (const float4*)(pc + (size_t)b * 3 * NP);
    float4* d4 = (float4*)spc;
    #pragma unroll 4
    for (int i = tid; i < (3 * NP) / 4; i += 256) d4[i] = src[i];
    for (int i = tid; i < 304; i += 256) {
        int ci = i >> 4, c2 = i & 15;
        swp[i] = pack2(w1[(2 * c2) * 19 + ci], w1[(2 * c2 + 1) * 19 + ci]);
    }
    if (tid < 16) sbp[tid] = pack2(b1[2 * tid], b1[2 * tid + 1]);
    if (tid < 32) { bss[tid] = 0.f; bsq[tid] = 0.f; }
    __syncthreads();

    #pragma unroll 1
    for (int qi = 0; qi < 4; qi++) {
        int q  = qb + w * 4 + qi;                  // global query id
        int sl = q & (SQ - 1);
        const float* np = newpc + (size_t)b * 3 * SQ + sl;
        float qx = np[0], qy = np[SQ], qz = np[2 * SQ];

        int count = 0, firstidx = 0;
        for (int j0 = 0; j0 < NP; j0 += 64) {
            int ja = j0 + lane, jb = ja + 32;
            float ax = spc[ja] - qx, ay = spc[NP + ja] - qy, az = spc[2 * NP + ja] - qz;
            float bx = spc[jb] - qx, by = spc[NP + jb] - qy, bz = spc[2 * NP + jb] - qz;
            bool ina = fmaf(ax, ax, fmaf(ay, ay, az * az)) < R2;
            bool inb = fmaf(bx, bx, fmaf(by, by, bz * bz)) < R2;
            unsigned ma = __ballot_sync(0xffffffffu, ina);
            unsigned mb = __ballot_sync(0xffffffffu, inb);
            if (ma | mb) {
                if (count == 0)
                    firstidx = ma ? (j0 + __ffs((int)ma) - 1)
                                  : (j0 + 32 + __ffs((int)mb) - 1);
                if (ina) {
                    int slot = count + __popc(ma & ((1u << lane) - 1u));
                    if (slot < KN) sIdx[w][slot] = ja;
                }
                int ca = count + __popc(ma);
                if (inb) {
                    int slot = ca + __popc(mb & ((1u << lane) - 1u));
                    if (slot < KN) sIdx[w][slot] = jb;
                }
                count = ca + __popc(mb);
                if (count >= KN) break;            // num only needed as >0
            }
        }
        if (lane >= count) sIdx[w][lane] = firstidx;
        if (lane == 0) g_valid[q] = (count > 0) ? 1 : 0;
        __syncwarp();
        int j = sIdx[w][lane];
        __syncwarp();                               // protect sIdx for next qi

        float x[19];
        x[0] = spc[j] - qx; x[1] = spc[NP + j] - qy; x[2] = spc[2 * NP + j] - qz;
        const float4* ft = (const float4*)(g_featT + ((size_t)b * NP + j) * CF);
        float4 f;
        f = ft[0]; x[3]  = f.x; x[4]  = f.y; x[5]  = f.z; x[6]  = f.w;
        f = ft[1]; x[7]  = f.x; x[8]  = f.y; x[9]  = f.z; x[10] = f.w;
        f = ft[2]; x[11] = f.x; x[12] = f.y; x[13] = f.z; x[14] = f.w;
        f = ft[3]; x[15] = f.x; x[16] = f.y; x[17] = f.z; x[18] = f.w;

        unsigned long long acc[16];
        #pragma unroll
        for (int c2 = 0; c2 < 16; c2++) acc[c2] = sbp[c2];
        #pragma unroll
        for (int i = 0; i < 19; i++) {
            unsigned long long xx = dup2(x[i]);
            const ulonglong2* wp = (const ulonglong2*)(swp + i * 16);
            #pragma unroll
            for (int c4 = 0; c4 < 8; c4++) {
                ulonglong2 wv = wp[c4];
                fma2(acc[2 * c4],     wv.x, xx);
                fma2(acc[2 * c4 + 1], wv.y, xx);
            }
        }
        float y[32], yq[32];
        #pragma unroll
        for (int c2 = 0; c2 < 16; c2++) {
            float2 u = unpack2(acc[c2]);
            y[2 * c2] = u.x; y[2 * c2 + 1] = u.y;
        }
        float4* dst = (float4*)(g_y1 + ((size_t)q * 32 + lane) * 32);
        #pragma unroll
        for (int c4 = 0; c4 < 8; c4++)
            dst[c4] = make_float4(y[4 * c4], y[4 * c4 + 1], y[4 * c4 + 2], y[4 * c4 + 3]);
        #pragma unroll
        for (int c = 0; c < 32; c++) yq[c] = y[c] * y[c];
        float osum, osq;
        warp_fold(y, yq, lane, osum, osq);
        atomicAdd(&bss[lane], osum);
        atomicAdd(&bsq[lane], osq);
    }
    __syncthreads();
    if (tid < 32) {
        atomicAdd(&g_stats[tid],      (double)bss[tid]);
        atomicAdd(&g_stats[32 + tid], (double)bsq[tid]);
    }
}

// ---------------- k2: BN1+ReLU + conv2 + stats2 -----------------------------
__global__ __launch_bounds__(256) void k2_kernel(
    const float* __restrict__ w2, const float* __restrict__ b2,
    const float* __restrict__ gam, const float* __restrict__ bet)
{
    __shared__ unsigned long long swp[512];
    __shared__ unsigned long long sbp[16];
    __shared__ float sa[32], sc[32];
    __shared__ float bss[32], bsq[32];
    int tid = threadIdx.x, lane = tid & 31;
    if (tid < 32) {
        double m = g_stats[tid] * INVP;
        double v = g_stats[32 + tid] * INVP - m * m;
        double a = (double)gam[tid] / sqrt(v + EPSD);
        sa[tid] = (float)a;
        sc[tid] = (float)((double)bet[tid] - m * a);
        bss[tid] = 0.f; bsq[tid] = 0.f;
    }
    if (tid < 16) sbp[tid] = pack2(b2[2 * tid], b2[2 * tid + 1]);
    for (int i = tid; i < 512; i += 256) {
        int ci = i >> 4, c2 = i & 15;
        swp[i] = pack2(w2[(2 * c2) * 32 + ci], w2[(2 * c2 + 1) * 32 + ci]);
    }
    __syncthreads();

    int p = blockIdx.x * 256 + tid;
    const float4* srcp = (const float4*)(g_y1 + (size_t)p * 32);
    float z[32];
    #pragma unroll
    for (int i = 0; i < 8; i++) {
        float4 v = srcp[i];
        z[4*i]   = fmaxf(fmaf(sa[4*i],   v.x, sc[4*i]),   0.f);
        z[4*i+1] = fmaxf(fmaf(sa[4*i+1], v.y, sc[4*i+1]), 0.f);
        z[4*i+2] = fmaxf(fmaf(sa[4*i+2], v.z, sc[4*i+2]), 0.f);
        z[4*i+3] = fmaxf(fmaf(sa[4*i+3], v.w, sc[4*i+3]), 0.f);
    }
    unsigned long long acc[16];
    #pragma unroll
    for (int c2 = 0; c2 < 16; c2++) acc[c2] = sbp[c2];
    #pragma unroll
    for (int i = 0; i < 32; i++) {
        unsigned long long xx = dup2(z[i]);
        const ulonglong2* wp = (const ulonglong2*)(swp + i * 16);
        #pragma unroll
        for (int c4 = 0; c4 < 8; c4++) {
            ulonglong2 wv = wp[c4];
            fma2(acc[2 * c4],     wv.x, xx);
            fma2(acc[2 * c4 + 1], wv.y, xx);
        }
    }
    float y[32], yq[32];
    #pragma unroll
    for (int c2 = 0; c2 < 16; c2++) {
        float2 u = unpack2(acc[c2]);
        y[2 * c2] = u.x; y[2 * c2 + 1] = u.y;
    }
    float4* dst = (float4*)(g_y2 + (size_t)p * 32);
    #pragma unroll
    for (int c4 = 0; c4 < 8; c4++)
        dst[c4] = make_float4(y[4*c4], y[4*c4+1], y[4*c4+2], y[4*c4+3]);
    #pragma unroll
    for (int c = 0; c < 32; c++) yq[c] = y[c] * y[c];
    float osum, osq;
    warp_fold(y, yq, lane, osum, osq);
    atomicAdd(&bss[lane], osum);
    atomicAdd(&bsq[lane], osq);
    __syncthreads();
    if (tid < 32) {
        atomicAdd(&g_stats[64 + tid], (double)bss[tid]);
        atomicAdd(&g_stats[96 + tid], (double)bsq[tid]);
    }
}

// ---------------- k3: BN2+ReLU + conv3 (32->64, warp-per-half) + stats3 -----
__global__ __launch_bounds__(256) void k3_kernel(
    const float* __restrict__ w3, const float* __restrict__ b3,
    const float* __restrict__ gam, const float* __restrict__ bet)
{
    __shared__ unsigned long long swp[32 * 32];  // [ci][pair]
    __shared__ unsigned long long sbp[32];
    __shared__ float sa[32], sc[32];
    __shared__ float bss[64], bsq[64];
    int tid = threadIdx.x, lane = tid & 31;
    if (tid < 32) {
        double m = g_stats[64 + tid] * INVP;
        double v = g_stats[96 + tid] * INVP - m * m;
        double a = (double)gam[tid] / sqrt(v + EPSD);
        sa[tid] = (float)a;
        sc[tid] = (float)((double)bet[tid] - m * a);
        sbp[tid] = pack2(b3[2 * tid], b3[2 * tid + 1]);
    }
    if (tid < 64) { bss[tid] = 0.f; bsq[tid] = 0.f; }
    for (int i = tid; i < 1024; i += 256) {
        int ci = i >> 5, c2 = i & 31;
        swp[i] = pack2(w3[(2 * c2) * 32 + ci], w3[(2 * c2 + 1) * 32 + ci]);
    }
    __syncthreads();

    int gw = blockIdx.x * 8 + (tid >> 5);        // global warp id
    int h  = gw & 1;                              // output-channel half
    int p  = (gw >> 1) * 32 + lane;               // point id
    const float4* srcp = (const float4*)(g_y2 + (size_t)p * 32);
    float z[32];
    #pragma unroll
    for (int i = 0; i < 8; i++) {
        float4 v = srcp[i];
        z[4*i]   = fmaxf(fmaf(sa[4*i],   v.x, sc[4*i]),   0.f);
        z[4*i+1] = fmaxf(fmaf(sa[4*i+1], v.y, sc[4*i+1]), 0.f);
        z[4*i+2] = fmaxf(fmaf(sa[4*i+2], v.z, sc[4*i+2]), 0.f);
        z[4*i+3] = fmaxf(fmaf(sa[4*i+3], v.w, sc[4*i+3]), 0.f);
    }
    unsigned long long acc[16];
    #pragma unroll
    for (int c2 = 0; c2 < 16; c2++) acc[c2] = sbp[h * 16 + c2];
    #pragma unroll
    for (int i = 0; i < 32; i++) {
        unsigned long long xx = dup2(z[i]);
        const ulonglong2* wp = (const ulonglong2*)(swp + i * 32 + h * 16);
        #pragma unroll
        for (int c4 = 0; c4 < 8; c4++) {
            ulonglong2 wv = wp[c4];
            fma2(acc[2 * c4],     wv.x, xx);
            fma2(acc[2 * c4 + 1], wv.y, xx);
        }
    }
    float y[32], yq[32];
    #pragma unroll
    for (int c2 = 0; c2 < 16; c2++) {
        float2 u = unpack2(acc[c2]);
        y[2 * c2] = u.x; y[2 * c2 + 1] = u.y;
    }
    float4* dst = (float4*)(g_y3 + (size_t)p * 64 + h * 32);
    #pragma unroll
    for (int c4 = 0; c4 < 8; c4++)
        dst[c4] = make_float4(y[4*c4], y[4*c4+1], y[4*c4+2], y[4*c4+3]);
    #pragma unroll
    for (int c = 0; c < 32; c++) yq[c] = y[c] * y[c];
    float osum, osq;
    warp_fold(y, yq, lane, osum, osq);
    atomicAdd(&bss[h * 32 + lane], osum);
    atomicAdd(&bsq[h * 32 + lane], osq);
    __syncthreads();
    if (tid < 64) {
        atomicAdd(&g_stats[128 + tid], (double)bss[tid]);
        atomicAdd(&g_stats[192 + tid], (double)bsq[tid]);
    }
}

// ---------------- k4: BN3+ReLU + valid mask + transpose to [B,64,S,K] ------
__global__ __launch_bounds__(256) void k4_kernel(
    float* __restrict__ out,
    const float* __restrict__ gam, const float* __restrict__ bet)
{
    __shared__ float tile[64 * 65];
    __shared__ float sa[64], sc[64];
    int tid = threadIdx.x;
    if (tid < 64) {
        double m = g_stats[128 + tid] * INVP;
        double v = g_stats[192 + tid] * INVP - m * m;
        double a = (double)gam[tid] / sqrt(v + EPSD);
        sa[tid] = (float)a;
        sc[tid] = (float)((double)bet[tid] - m * a);
    }
    __syncthreads();

    int pt0 = blockIdx.x * 64;
    int b   = pt0 >> 16;
    int w0  = pt0 & 65535;
    const float* srcp = g_y3 + (size_t)pt0 * 64;
    #pragma unroll
    for (int it = 0; it < 16; it++) {
        int flat = it * 256 + tid;
        int p = flat >> 6, c = flat & 63;
        float val = fmaxf(fmaf(sa[c], srcp[flat], sc[c]), 0.f);
        val *= (float)g_valid[(pt0 + p) >> 5];
        tile[p * 65 + c] = val;
    }
    __syncthreads();
    float* ob = out + (size_t)b * 64 * 65536 + w0;
    #pragma unroll
    for (int it = 0; it < 16; it++) {
        int flat = it * 256 + tid;
        int c = flat >> 6, p = flat & 63;
        ob[(size_t)c * 65536 + p] = tile[p * 65 + c];
    }
}

// ---------------- launch ---------------------------------------------------
extern "C" void kernel_launch(void* const* d_in, const int* in_sizes, int n_in,
                              void* d_out, int out_size)
{
    const float* pc   = (const float*)d_in[0];
    const float* feat = (const float*)d_in[1];
    const float* npc  = (const float*)d_in[2];
    const float* w1   = (const float*)d_in[3];
    const float* b1   = (const float*)d_in[4];
    const float* g1   = (const float*)d_in[5];
    const float* be1  = (const float*)d_in[6];
    const float* w2   = (const float*)d_in[7];
    const float* b2   = (const float*)d_in[8];
    const float* g2   = (const float*)d_in[9];
    const float* be2  = (const float*)d_in[10];
    const float* w3   = (const float*)d_in[11];
    const float* b3   = (const float*)d_in[12];
    const float* g3   = (const float*)d_in[13];
    const float* be3  = (const float*)d_in[14];
    float* out = (float*)d_out;

    cudaFuncSetAttribute(k1_kernel, cudaFuncAttributeMaxDynamicSharedMemorySize,
                         3 * NP * sizeof(float));

    prep_kernel<<<512, 256>>>(feat);                       // zero stats + featT
    k1_kernel<<<256, 256, 3 * NP * sizeof(float)>>>(pc, npc, w1, b1);
    k2_kernel<<<1024, 256>>>(w2, b2, g1, be1);
    k3_kernel<<<2048, 256>>>(w3, b3, g2, be2);
    k4_kernel<<<4096, 256>>>(out, g3, be3);
}

// round 5
// speedup vs baseline: 1.7475x; 1.0192x over previous
#include <cuda_runtime.h>

#define BQ 4
#define NP 8192
#define SQ 2048
#define CF 16
#define KN 32
constexpr int    P    = BQ * SQ * KN;        // 262144 points
constexpr float  R2   = 0.25f;
constexpr double EPSD = 1e-5;
constexpr double INVP = 1.0 / (double)P;

// ---------------- scratch ----------------
__device__ int    g_valid[BQ * SQ];
__device__ float  g_featT[(size_t)BQ * NP * CF];   // [b][j][c] point-major
__device__ float  g_y1[(size_t)P * 32];
__device__ float  g_y2[(size_t)P * 32];
__device__ float  g_y3[(size_t)P * 64];
// [0:32)sum1 [32:64)sq1 [64:96)sum2 [96:128)sq2 [128:192)sum3 [192:256)sq3
__device__ double g_stats[256];

// ---------------- f32x2 helpers ----------------
__device__ __forceinline__ unsigned long long pack2(float a, float b) {
    unsigned long long r;
    asm("mov.b64 %0, {%1, %2};" : "=l"(r) : "f"(a), "f"(b));
    return r;
}
__device__ __forceinline__ unsigned long long dup2(float a) {
    unsigned long long r;
    asm("mov.b64 %0, {%1, %1};" : "=l"(r) : "f"(a));
    return r;
}
__device__ __forceinline__ void fma2(unsigned long long& d,
                                     unsigned long long a, unsigned long long b) {
    asm("fma.rn.f32x2 %0, %1, %2, %0;" : "+l"(d) : "l"(a), "l"(b));
}
__device__ __forceinline__ void add2(unsigned long long& d, unsigned long long a) {
    asm("add.rn.f32x2 %0, %0, %1;" : "+l"(d) : "l"(a));
}
__device__ __forceinline__ float2 unpack2(unsigned long long v) {
    float lo, hi;
    asm("mov.b64 {%0, %1}, %2;" : "=f"(lo), "=f"(hi) : "l"(v));
    return make_float2(lo, hi);
}

// Warp transpose-fold (used only in k1).
__device__ __forceinline__ void warp_fold(float* s, float* t, int lane,
                                          float& osum, float& osq) {
    #pragma unroll
    for (int st = 0; st < 5; st++) {
        int wbit = 1 << st;
        bool hi = (lane & wbit) != 0;
        #pragma unroll
        for (int k = 0; k < (16 >> st); k++) {
            float slo = s[2 * k], shi = s[2 * k + 1];
            float ssend = hi ? slo : shi;
            float skeep = hi ? shi : slo;
            s[k] = skeep + __shfl_xor_sync(0xffffffffu, ssend, wbit);
            float tlo = t[2 * k], thi = t[2 * k + 1];
            float tsend = hi ? tlo : thi;
            float tkeep = hi ? thi : tlo;
            t[k] = tkeep + __shfl_xor_sync(0xffffffffu, tsend, wbit);
        }
    }
    osum = s[0]; osq = t[0];
}

// ---------------- prep: zero stats + transpose feat to point-major ----------
__global__ __launch_bounds__(256) void prep_kernel(const float* __restrict__ feat) {
    __shared__ float tile[16][65];
    int tid = threadIdx.x;
    if (blockIdx.x == 0) g_stats[tid] = 0.0;
    int b  = blockIdx.x >> 7;
    int j0 = (blockIdx.x & 127) * 64;
    const float* f = feat + (size_t)b * CF * NP;
    #pragma unroll
    for (int i = tid; i < 1024; i += 256) {
        int c = i >> 6, jj = i & 63;
        tile[c][jj] = f[(size_t)c * NP + j0 + jj];
    }
    __syncthreads();
    float* o = g_featT + ((size_t)b * NP + j0) * CF;
    #pragma unroll
    for (int i = tid; i < 1024; i += 256) {
        int jj = i >> 4, c = i & 15;
        o[i] = tile[c][jj];
    }
}

// ---------------- k1: ball query + gather + conv1 + stats1 -----------------
__global__ __launch_bounds__(256) void k1_kernel(
    const float* __restrict__ pc, const float* __restrict__ newpc,
    const float* __restrict__ w1, const float* __restrict__ b1)
{
    extern __shared__ float spc[];                 // 3*NP floats (96 KB)
    __shared__ unsigned long long swp[19 * 16];
    __shared__ unsigned long long sbp[16];
    __shared__ float bss[32], bsq[32];
    __shared__ int   sIdx[8][KN];

    int tid = threadIdx.x, lane = tid & 31, w = tid >> 5;
    int qb = blockIdx.x * 32;
    int b  = qb >> 11;

    const float4* src = (const float4*)(pc + (size_t)b * 3 * NP);
    float4* d4 = (float4*)spc;
    #pragma unroll 4
    for (int i = tid; i < (3 * NP) / 4; i += 256) d4[i] = src[i];
    for (int i = tid; i < 304; i += 256) {
        int ci = i >> 4, c2 = i & 15;
        swp[i] = pack2(w1[(2 * c2) * 19 + ci], w1[(2 * c2 + 1) * 19 + ci]);
    }
    if (tid < 16) sbp[tid] = pack2(b1[2 * tid], b1[2 * tid + 1]);
    if (tid < 32) { bss[tid] = 0.f; bsq[tid] = 0.f; }
    __syncthreads();

    #pragma unroll 1
    for (int qi = 0; qi < 4; qi++) {
        int q  = qb + w * 4 + qi;
        int sl = q & (SQ - 1);
        const float* np = newpc + (size_t)b * 3 * SQ + sl;
        float qx = np[0], qy = np[SQ], qz = np[2 * SQ];

        int count = 0, firstidx = 0;
        for (int j0 = 0; j0 < NP; j0 += 64) {
            int ja = j0 + lane, jb = ja + 32;
            float ax = spc[ja] - qx, ay = spc[NP + ja] - qy, az = spc[2 * NP + ja] - qz;
            float bx = spc[jb] - qx, by = spc[NP + jb] - qy, bz = spc[2 * NP + jb] - qz;
            bool ina = fmaf(ax, ax, fmaf(ay, ay, az * az)) < R2;
            bool inb = fmaf(bx, bx, fmaf(by, by, bz * bz)) < R2;
            unsigned ma = __ballot_sync(0xffffffffu, ina);
            unsigned mb = __ballot_sync(0xffffffffu, inb);
            if (ma | mb) {
                if (count == 0)
                    firstidx = ma ? (j0 + __ffs((int)ma) - 1)
                                  : (j0 + 32 + __ffs((int)mb) - 1);
                if (ina) {
                    int slot = count + __popc(ma & ((1u << lane) - 1u));
                    if (slot < KN) sIdx[w][slot] = ja;
                }
                int ca = count + __popc(ma);
                if (inb) {
                    int slot = ca + __popc(mb & ((1u << lane) - 1u));
                    if (slot < KN) sIdx[w][slot] = jb;
                }
                count = ca + __popc(mb);
                if (count >= KN) break;
            }
        }
        if (lane >= count) sIdx[w][lane] = firstidx;
        if (lane == 0) g_valid[q] = (count > 0) ? 1 : 0;
        __syncwarp();
        int j = sIdx[w][lane];
        __syncwarp();

        float x[19];
        x[0] = spc[j] - qx; x[1] = spc[NP + j] - qy; x[2] = spc[2 * NP + j] - qz;
        const float4* ft = (const float4*)(g_featT + ((size_t)b * NP + j) * CF);
        float4 f;
        f = ft[0]; x[3]  = f.x; x[4]  = f.y; x[5]  = f.z; x[6]  = f.w;
        f = ft[1]; x[7]  = f.x; x[8]  = f.y; x[9]  = f.z; x[10] = f.w;
        f = ft[2]; x[11] = f.x; x[12] = f.y; x[13] = f.z; x[14] = f.w;
        f = ft[3]; x[15] = f.x; x[16] = f.y; x[17] = f.z; x[18] = f.w;

        unsigned long long acc[16];
        #pragma unroll
        for (int c2 = 0; c2 < 16; c2++) acc[c2] = sbp[c2];
        #pragma unroll
        for (int i = 0; i < 19; i++) {
            unsigned long long xx = dup2(x[i]);
            const ulonglong2* wp = (const ulonglong2*)(swp + i * 16);
            #pragma unroll
            for (int c4 = 0; c4 < 8; c4++) {
                ulonglong2 wv = wp[c4];
                fma2(acc[2 * c4],     wv.x, xx);
                fma2(acc[2 * c4 + 1], wv.y, xx);
            }
        }
        float y[32], yq[32];
        #pragma unroll
        for (int c2 = 0; c2 < 16; c2++) {
            float2 u = unpack2(acc[c2]);
            y[2 * c2] = u.x; y[2 * c2 + 1] = u.y;
        }
        float4* dst = (float4*)(g_y1 + ((size_t)q * 32 + lane) * 32);
        #pragma unroll
        for (int c4 = 0; c4 < 8; c4++)
            dst[c4] = make_float4(y[4 * c4], y[4 * c4 + 1], y[4 * c4 + 2], y[4 * c4 + 3]);
        #pragma unroll
        for (int c = 0; c < 32; c++) yq[c] = y[c] * y[c];
        float osum, osq;
        warp_fold(y, yq, lane, osum, osq);
        atomicAdd(&bss[lane], osum);
        atomicAdd(&bsq[lane], osq);
    }
    __syncthreads();
    if (tid < 32) {
        atomicAdd(&g_stats[tid],      (double)bss[tid]);
        atomicAdd(&g_stats[32 + tid], (double)bsq[tid]);
    }
}

// ---------------- k2: BN1+ReLU + conv2 (reg-weights, point-pair) + stats2 ---
// 2048 blocks x 256 threads; tile = 128 points = 64 point-pairs.
// Thread owns channel c = tid&31, weights duplicated in regs; streams pairs.
__global__ __launch_bounds__(256) void k2_kernel(
    const float* __restrict__ w2, const float* __restrict__ b2,
    const float* __restrict__ gam, const float* __restrict__ bet)
{
    __shared__ float z2[64 * 64];       // [ppair][i*2+h] interleaved, 16 KB
    __shared__ float sw[1024];
    __shared__ float sa[32], sc[32];
    __shared__ float bss[32], bsq[32];
    int tid = threadIdx.x;

    for (int i = tid; i < 1024; i += 256) sw[i] = w2[i];
    if (tid < 32) {
        double m = g_stats[tid] * INVP;
        double v = g_stats[32 + tid] * INVP - m * m;
        double a = (double)gam[tid] / sqrt(v + EPSD);
        sa[tid] = (float)a;
        sc[tid] = (float)((double)bet[tid] - m * a);
        bss[tid] = 0.f; bsq[tid] = 0.f;
    }
    __syncthreads();

    // Stage z tile: read y1 (coalesced float4), BN1+ReLU, write pair-interleaved.
    int p0 = blockIdx.x * 128;
    const float4* y4 = (const float4*)(g_y1 + (size_t)p0 * 32);
    #pragma unroll
    for (int k = 0; k < 4; k++) {
        int lf = tid + 256 * k;          // [0,1024)
        int lp = lf >> 3, c0 = (lf & 7) * 4;
        float4 v = y4[lf];
        float* zb = z2 + (lp >> 1) * 64 + (lp & 1);
        zb[(c0 + 0) * 2] = fmaxf(fmaf(sa[c0 + 0], v.x, sc[c0 + 0]), 0.f);
        zb[(c0 + 1) * 2] = fmaxf(fmaf(sa[c0 + 1], v.y, sc[c0 + 1]), 0.f);
        zb[(c0 + 2) * 2] = fmaxf(fmaf(sa[c0 + 2], v.z, sc[c0 + 2]), 0.f);
        zb[(c0 + 3) * 2] = fmaxf(fmaf(sa[c0 + 3], v.w, sc[c0 + 3]), 0.f);
    }

    int c   = tid & 31;
    int ppg = tid >> 5;                  // 8 groups x 8 pairs
    unsigned long long wdup[32], breg;
    #pragma unroll
    for (int i = 0; i < 32; i++) wdup[i] = dup2(sw[c * 32 + i]);
    breg = dup2(b2[c]);
    __syncthreads();

    unsigned long long ssum = 0, ssqr = 0;
    #pragma unroll 1
    for (int t = 0; t < 8; t++) {
        int pp = ppg * 8 + t;
        const ulonglong2* r2 = (const ulonglong2*)(z2 + pp * 64);
        unsigned long long acc = breg;
        #pragma unroll
        for (int k = 0; k < 16; k++) {
            ulonglong2 lv = r2[k];
            fma2(acc, wdup[2 * k],     lv.x);
            fma2(acc, wdup[2 * k + 1], lv.y);
        }
        float2 u = unpack2(acc);
        int pA = p0 + pp * 2;
        g_y2[(size_t)pA * 32 + c]       = u.x;
        g_y2[(size_t)(pA + 1) * 32 + c] = u.y;
        add2(ssum, acc);
        fma2(ssqr, acc, acc);
    }
    float2 s = unpack2(ssum), q = unpack2(ssqr);
    atomicAdd(&bss[c], s.x + s.y);
    atomicAdd(&bsq[c], q.x + q.y);
    __syncthreads();
    if (tid < 32) {
        atomicAdd(&g_stats[64 + tid], (double)bss[tid]);
        atomicAdd(&g_stats[96 + tid], (double)bsq[tid]);
    }
}

// ---------------- k3: BN2+ReLU + conv3 (32->64) + stats3 --------------------
// 2048 blocks x 256 threads; tile = 128 points = 64 point-pairs.
// Thread owns channel c = tid&63 (4 pair-groups of 16 pairs each).
__global__ __launch_bounds__(256) void k3_kernel(
    const float* __restrict__ w3, const float* __restrict__ b3,
    const float* __restrict__ gam, const float* __restrict__ bet)
{
    __shared__ float z2[64 * 64];       // 16 KB
    __shared__ float sw[2048];
    __shared__ float sa[32], sc[32];
    __shared__ float bss[64], bsq[64];
    int tid = threadIdx.x;

    for (int i = tid; i < 2048; i += 256) sw[i] = w3[i];
    if (tid < 32) {
        double m = g_stats[64 + tid] * INVP;
        double v = g_stats[96 + tid] * INVP - m * m;
        double a = (double)gam[tid] / sqrt(v + EPSD);
        sa[tid] = (float)a;
        sc[tid] = (float)((double)bet[tid] - m * a);
    }
    if (tid < 64) { bss[tid] = 0.f; bsq[tid] = 0.f; }
    __syncthreads();

    int p0 = blockIdx.x * 128;
    const float4* y4 = (const float4*)(g_y2 + (size_t)p0 * 32);
    #pragma unroll
    for (int k = 0; k < 4; k++) {
        int lf = tid + 256 * k;
        int lp = lf >> 3, c0 = (lf & 7) * 4;
        float4 v = y4[lf];
        float* zb = z2 + (lp >> 1) * 64 + (lp & 1);
        zb[(c0 + 0) * 2] = fmaxf(fmaf(sa[c0 + 0], v.x, sc[c0 + 0]), 0.f);
        zb[(c0 + 1) * 2] = fmaxf(fmaf(sa[c0 + 1], v.y, sc[c0 + 1]), 0.f);
        zb[(c0 + 2) * 2] = fmaxf(fmaf(sa[c0 + 2], v.z, sc[c0 + 2]), 0.f);
        zb[(c0 + 3) * 2] = fmaxf(fmaf(sa[c0 + 3], v.w, sc[c0 + 3]), 0.f);
    }

    int c   = tid & 63;
    int ppg = tid >> 6;                  // 4 groups x 16 pairs
    unsigned long long wdup[32], breg;
    #pragma unroll
    for (int i = 0; i < 32; i++) wdup[i] = dup2(sw[c * 32 + i]);
    breg = dup2(b3[c]);
    __syncthreads();

    unsigned long long ssum = 0, ssqr = 0;
    #pragma unroll 1
    for (int t = 0; t < 16; t++) {
        int pp = ppg * 16 + t;
        const ulonglong2* r2 = (const ulonglong2*)(z2 + pp * 64);
        unsigned long long acc = breg;
        #pragma unroll
        for (int k = 0; k < 16; k++) {
            ulonglong2 lv = r2[k];
            fma2(acc, wdup[2 * k],     lv.x);
            fma2(acc, wdup[2 * k + 1], lv.y);
        }
        float2 u = unpack2(acc);
        int pA = p0 + pp * 2;
        g_y3[(size_t)pA * 64 + c]       = u.x;
        g_y3[(size_t)(pA + 1) * 64 + c] = u.y;
        add2(ssum, acc);
        fma2(ssqr, acc, acc);
    }
    float2 s = unpack2(ssum), q = unpack2(ssqr);
    atomicAdd(&bss[c], s.x + s.y);
    atomicAdd(&bsq[c], q.x + q.y);
    __syncthreads();
    if (tid < 64) {
        atomicAdd(&g_stats[128 + tid], (double)bss[tid]);
        atomicAdd(&g_stats[192 + tid], (double)bsq[tid]);
    }
}

// ---------------- k4: BN3+ReLU + valid mask + transpose to [B,64,S,K] ------
__global__ __launch_bounds__(256) void k4_kernel(
    float* __restrict__ out,
    const float* __restrict__ gam, const float* __restrict__ bet)
{
    __shared__ float tile[64 * 65];
    __shared__ float sa[64], sc[64];
    int tid = threadIdx.x;
    if (tid < 64) {
        double m = g_stats[128 + tid] * INVP;
        double v = g_stats[192 + tid] * INVP - m * m;
        double a = (double)gam[tid] / sqrt(v + EPSD);
        sa[tid] = (float)a;
        sc[tid] = (float)((double)bet[tid] - m * a);
    }
    __syncthreads();

    int pt0 = blockIdx.x * 64;
    int b   = pt0 >> 16;
    int w0  = pt0 & 65535;
    const float* srcp = g_y3 + (size_t)pt0 * 64;
    #pragma unroll
    for (int it = 0; it < 16; it++) {
        int flat = it * 256 + tid;
        int p = flat >> 6, c = flat & 63;
        float val = fmaxf(fmaf(sa[c], srcp[flat], sc[c]), 0.f);
        val *= (float)g_valid[(pt0 + p) >> 5];
        tile[p * 65 + c] = val;
    }
    __syncthreads();
    float* ob = out + (size_t)b * 64 * 65536 + w0;
    #pragma unroll
    for (int it = 0; it < 16; it++) {
        int flat = it * 256 + tid;
        int c = flat >> 6, p = flat & 63;
        ob[(size_t)c * 65536 + p] = tile[p * 65 + c];
    }
}

// ---------------- launch ---------------------------------------------------
extern "C" void kernel_launch(void* const* d_in, const int* in_sizes, int n_in,
                              void* d_out, int out_size)
{
    const float* pc   = (const float*)d_in[0];
    const float* feat = (const float*)d_in[1];
    const float* npc  = (const float*)d_in[2];
    const float* w1   = (const float*)d_in[3];
    const float* b1   = (const float*)d_in[4];
    const float* g1   = (const float*)d_in[5];
    const float* be1  = (const float*)d_in[6];
    const float* w2   = (const float*)d_in[7];
    const float* b2   = (const float*)d_in[8];
    const float* g2   = (const float*)d_in[9];
    const float* be2  = (const float*)d_in[10];
    const float* w3   = (const float*)d_in[11];
    const float* b3   = (const float*)d_in[12];
    const float* g3   = (const float*)d_in[13];
    const float* be3  = (const float*)d_in[14];
    float* out = (float*)d_out;

    cudaFuncSetAttribute(k1_kernel, cudaFuncAttributeMaxDynamicSharedMemorySize,
                         3 * NP * sizeof(float));

    prep_kernel<<<512, 256>>>(feat);
    k1_kernel<<<256, 256, 3 * NP * sizeof(float)>>>(pc, npc, w1, b1);
    k2_kernel<<<2048, 256>>>(w2, b2, g1, be1);
    k3_kernel<<<2048, 256>>>(w3, b3, g2, be2);
    k4_kernel<<<4096, 256>>>(out, g3, be3);
}